// round 4
// baseline (speedup 1.0000x reference)
#include <cuda_runtime.h>
#include <cuda_bf16.h>
#include <cstdint>

// Problem constants (fixed by the bench's setup_inputs)
// NUM=32, NUM_TOP=32, COBJ=4, B=300, D=256, H=256, K=8 (patch 4x4), L=128

// Scratch: H (post-GEMM hidden activations, +b1 folded in), stored TRANSPOSED
// as [side][n][h(256)][a(128)] so phase 2 streams it with clean float4 loads.
__device__ __align__(16) float g_Ht[2 * 32 * 256 * 128];   // 8.4 MB

// ---------------- packed f32x2 helpers (Blackwell FFMA2) ----------------
__device__ __forceinline__ unsigned long long pk2(float x, float y) {
    unsigned long long r;
    asm("mov.b64 %0, {%1, %2};" : "=l"(r)
        : "r"(__float_as_uint(x)), "r"(__float_as_uint(y)));
    return r;
}
__device__ __forceinline__ void upk2(unsigned long long v, float& x, float& y) {
    unsigned int lo, hi;
    asm("mov.b64 {%0, %1}, %2;" : "=r"(lo), "=r"(hi) : "l"(v));
    x = __uint_as_float(lo); y = __uint_as_float(hi);
}
__device__ __forceinline__ unsigned long long fma2(unsigned long long a,
                                                   unsigned long long b,
                                                   unsigned long long c) {
    unsigned long long d;
    asm("fma.rn.f32x2 %0, %1, %2, %3;" : "=l"(d) : "l"(a), "l"(b), "l"(c));
    return d;
}

// ---------------- Phase 1: gather + GEMM (+b1), store transposed ----------
// block id: [n(32)] x [side(2)] x [half(2)] = 128 blocks, 256 threads.
// Each block computes C[64 rows][256 cols] = A_gathered[64,256] @ W[256,256].
__global__ __launch_bounds__(256)
void k_gemm(const float* __restrict__ fea,
            const int* __restrict__ ind0, const int* __restrict__ ind1,
            const float* __restrict__ W1a, const float* __restrict__ W1b,
            const float* __restrict__ b1)
{
    const int id   = blockIdx.x;
    const int n    = id >> 2;
    const int side = (id >> 1) & 1;
    const int half = id & 1;
    const int* __restrict__ ind = side ? ind1 : ind0;
    const float* __restrict__ W = side ? W1b : W1a;

    __shared__ __align__(16) float As[64][32];
    __shared__ __align__(16) float Bs[32][256];
    __shared__ int rowOff[64];

    const int tid = threadIdx.x;
    if (tid < 64) {
        int a = half * 64 + tid;
        int t = a >> 2, c = a & 3;
        int b = ind[(n * 32 + t) * 4 + c];
        rowOff[tid] = ((n * 8 + side * 4 + c) * 300 + b) * 256;
    }
    __syncthreads();

    const int rowg = tid >> 5;      // 0..7 (warp id)
    const int colg = tid & 31;      // 0..31
    const int r0   = rowg * 8;
    const int cA   = colg * 4;      // col groups: [cA..cA+3] and [128+cA..128+cA+3]

    // 8 rows x 8 cols as 8x4 packed f32x2 accumulators
    unsigned long long acc2[8][4];
#pragma unroll
    for (int i = 0; i < 8; i++)
#pragma unroll
        for (int u = 0; u < 4; u++) acc2[i][u] = 0ull;

    for (int kt = 0; kt < 8; kt++) {
        const int d0 = kt * 32;
        // A tile: 64x32 = 512 float4, 2 per thread (gathered rows)
#pragma unroll
        for (int p = 0; p < 2; p++) {
            int f4 = tid + p * 256;
            int r = f4 >> 3, q = f4 & 7;
            float4 v = *(const float4*)(fea + rowOff[r] + d0 + q * 4);
            *(float4*)&As[r][q * 4] = v;
        }
        // B tile: 32x256 = 2048 float4, 8 per thread
#pragma unroll
        for (int p = 0; p < 8; p++) {
            int f4 = tid + p * 256;
            int kr = f4 >> 6, q = f4 & 63;
            float4 v = *(const float4*)(W + (d0 + kr) * 256 + q * 4);
            *(float4*)&Bs[kr][q * 4] = v;
        }
        __syncthreads();

#pragma unroll 4
        for (int k = 0; k < 32; k++) {
            float4 bb0 = *(float4*)&Bs[k][cA];
            float4 bb1 = *(float4*)&Bs[k][128 + cA];
            unsigned long long bp0 = pk2(bb0.x, bb0.y);
            unsigned long long bp1 = pk2(bb0.z, bb0.w);
            unsigned long long bp2 = pk2(bb1.x, bb1.y);
            unsigned long long bp3 = pk2(bb1.z, bb1.w);
#pragma unroll
            for (int i = 0; i < 8; i++) {
                float av = As[r0 + i][k];            // warp-uniform broadcast
                unsigned long long a2 = pk2(av, av);
                acc2[i][0] = fma2(a2, bp0, acc2[i][0]);
                acc2[i][1] = fma2(a2, bp1, acc2[i][1]);
                acc2[i][2] = fma2(a2, bp2, acc2[i][2]);
                acc2[i][3] = fma2(a2, bp3, acc2[i][3]);
            }
        }
        __syncthreads();
    }

    // Unpack, add b1, store transposed: g_Ht[side][n][col][a]
    float accf[8][8];
#pragma unroll
    for (int i = 0; i < 8; i++)
#pragma unroll
        for (int u = 0; u < 4; u++)
            upk2(acc2[i][u], accf[i][2 * u], accf[i][2 * u + 1]);

    int cols[8];
#pragma unroll
    for (int u = 0; u < 4; u++) { cols[u] = cA + u; cols[4 + u] = 128 + cA + u; }

    float* base = g_Ht + (size_t)(side * 32 + n) * 256 * 128 + half * 64 + r0;
#pragma unroll
    for (int j = 0; j < 8; j++) {
        const int col = cols[j];
        const float bias = b1[col];
        float4 v0 = make_float4(accf[0][j] + bias, accf[1][j] + bias,
                                accf[2][j] + bias, accf[3][j] + bias);
        float4 v1 = make_float4(accf[4][j] + bias, accf[5][j] + bias,
                                accf[6][j] + bias, accf[7][j] + bias);
        float* dst = base + (size_t)col * 128;
        *(float4*)dst       = v0;
        *(float4*)(dst + 4) = v1;
    }
}

// ---------------- Phase 2: pairwise relu-relation + fused 4x4 patch sum ---
// block: [n(32)] x [atile(4) of 32 a-rows] = 128 blocks, 256 threads.
// thread (i,j): i = patch-row within a-tile (0..7), j = patch-col (0..31).
// Accumulates S[n, atile*8+i, j] = sum_h sum_{4a x 4b} relu(h0+h1)*w[h]
__global__ __launch_bounds__(256)
void k_pair(const float* __restrict__ W2, const float* __restrict__ b2,
            float* __restrict__ out, int write_pairs)
{
    const int n     = blockIdx.x >> 2;
    const int atile = blockIdx.x & 3;
    const int a0    = atile * 32;
    const int tid   = threadIdx.x;
    const int i     = tid >> 5;     // warp id -> patch row
    const int j     = tid & 31;     // lane -> patch col

    __shared__ __align__(16) float S0[32][32];    // [h][a-tile]
    __shared__ __align__(16) float S1[32][128];   // [h][b]
    __shared__ float ws[32];

    const float* __restrict__ H0 = g_Ht + (size_t)n * 256 * 128;
    const float* __restrict__ H1 = g_Ht + (size_t)(32 + n) * 256 * 128;

    float acc = 0.f;
    for (int hc = 0; hc < 8; hc++) {
        const int h0 = hc * 32;
        if (tid < 32) ws[tid] = W2[h0 + tid];
        {   // S0: 1024 floats = 256 float4, 1 per thread
            int h = tid >> 3, q = tid & 7;
            *(float4*)&S0[h][q * 4] =
                *(const float4*)(H0 + (size_t)(h0 + h) * 128 + a0 + q * 4);
        }
#pragma unroll
        for (int p = 0; p < 4; p++) {  // S1: 4096 floats = 1024 float4
            int f4 = tid + p * 256;
            int h = f4 >> 5, q = f4 & 31;
            *(float4*)&S1[h][q * 4] =
                *(const float4*)(H1 + (size_t)(h0 + h) * 128 + q * 4);
        }
        __syncthreads();

#pragma unroll 4
        for (int h = 0; h < 32; h++) {
            const float w  = ws[h];
            const float4 A = *(float4*)&S0[h][4 * i];   // warp-uniform broadcast
            const float4 B = *(float4*)&S1[h][4 * j];   // coalesced
            float s;
            s  = fmaxf(A.x + B.x, 0.f);
            s += fmaxf(A.x + B.y, 0.f);
            s += fmaxf(A.x + B.z, 0.f);
            s += fmaxf(A.x + B.w, 0.f);
            s += fmaxf(A.y + B.x, 0.f);
            s += fmaxf(A.y + B.y, 0.f);
            s += fmaxf(A.y + B.z, 0.f);
            s += fmaxf(A.y + B.w, 0.f);
            s += fmaxf(A.z + B.x, 0.f);
            s += fmaxf(A.z + B.y, 0.f);
            s += fmaxf(A.z + B.z, 0.f);
            s += fmaxf(A.z + B.w, 0.f);
            s += fmaxf(A.w + B.x, 0.f);
            s += fmaxf(A.w + B.y, 0.f);
            s += fmaxf(A.w + B.z, 0.f);
            s += fmaxf(A.w + B.w, 0.f);
            acc = fmaf(s, w, acc);
        }
        __syncthreads();
    }

    const float val = acc + 16.0f * b2[0];
    const int m = atile * 8 + i;
    const int p = m * 32 + j;
    out[n * 1024 + p] = val;
    if (write_pairs) {
        float* pr = out + 32768 + ((size_t)n * 1024 + p) * 2;
        pr[0] = (float)m;
        pr[1] = (float)j;
    }
}

extern "C" void kernel_launch(void* const* d_in, const int* in_sizes, int n_in,
                              void* d_out, int out_size)
{
    (void)in_sizes;
    const float* fea  = (const float*)d_in[0];
    const int*   ind0 = (const int*)d_in[1];
    const int*   ind1 = (const int*)d_in[2];
    // 'k' may or may not be materialized as a device input (it is a python int
    // in the reference). If present it sits at index 3; weights follow.
    const int base = (n_in >= 9) ? 4 : 3;
    const float* W1a = (const float*)d_in[base + 0];
    const float* W1b = (const float*)d_in[base + 1];
    const float* b1  = (const float*)d_in[base + 2];
    const float* W2  = (const float*)d_in[base + 3];
    const float* b2  = (const float*)d_in[base + 4];
    float* out = (float*)d_out;

    const int write_pairs = (out_size >= 3 * 32768) ? 1 : 0;

    k_gemm<<<128, 256>>>(fea, ind0, ind1, W1a, W1b, b1);
    k_pair<<<128, 256>>>(W2, b2, out, write_pairs);
}